// round 10
// baseline (speedup 1.0000x reference)
#include <cuda_runtime.h>
#include <stdint.h>

// ---------------------------------------------------------------------------
// MagnitudePruning via 2-level-sampled key-window radix select on
// s = t*magnitude + |x|  (monotone surrogate; uniform divide preserves rank).
//
// zero    : clear small histograms/counters
// sample  : persistent 2-phase, chunked coalesced sampling (1M samples):
//           coarse 4096-bin hist -> coarse window -> runtime shift fs ->
//           fine 4096-bin hist (samples L2-hot) -> key window [k_lo,k_hi)
// passA   : ONE full fused streaming pass (no tiles, MLP-8 loads):
//           exact below-count, final out for out-of-window, warp-ballot
//           direct compaction of window cands, 2048-bin fine whist
// resolve : persistent: select fine bin b1+r1; ONE unrolled region stream
//           (finalize key>=b1_end, stash+low-hist b1 cands); block0 ->
//           exact thr; apply from stash. Exact fallback on any miss.
// ---------------------------------------------------------------------------

#define NBLOCKS    1184u
#define NTHREADS   256u
#define PER_BLOCK  40960u
#define STASH_MAX  512u
#define NCHUNKS    2048u
#define CHUNK_F4   128u

__device__ unsigned g_coarse[4096];
__device__ unsigned g_fine[4096];
__device__ unsigned g_whist[2048];
__device__ unsigned g_lowh[4096];
__device__ unsigned g_below;
__device__ unsigned g_done1, g_done2, g_d2;
__device__ unsigned g_s2r, g_rdy2;
__device__ unsigned g_ovf;
__device__ unsigned g_wbase, g_fs, g_tlo, g_thi;
__device__ unsigned g_klo, g_khi;
__device__ unsigned g_thr_key;
__device__ unsigned g_blk_cnt[NBLOCKS];
__device__ uint2    g_cand[NBLOCKS * PER_BLOCK];

__device__ __forceinline__ unsigned key_of(float x, float m, float tf) {
    float s = __fadd_rn(__fmul_rn(tf, m), fabsf(x));
    return __float_as_uint(s);
}
__device__ __forceinline__ float read_tf(const int* t_ptr) {
    return t_ptr ? (float)(*t_ptr) : 1.0f;
}
__device__ __forceinline__ unsigned rank_R(const float* sp, unsigned n) {
    float fidx = floorf(__fsub_rn(__fmul_rn(sp[0], (float)n), 1.0f));
    long long idx = (long long)fidx;
    if (idx < 0) idx = 0;
    if (idx > (long long)(n - 1)) idx = (long long)(n - 1);
    return (unsigned)idx + 1u;
}
__device__ __forceinline__ void agg_shared_add(unsigned* hist, unsigned bin) {
    unsigned act    = __activemask();
    unsigned peers  = __match_any_sync(act, bin);
    int      leader = __ffs(peers) - 1;
    if ((int)(threadIdx.x & 31) == leader)
        atomicAdd(&hist[bin], (unsigned)__popc(peers));
}

// ---------------------------------------------------------------------------
__global__ void zero_kernel() {
    unsigned tid = blockIdx.x * blockDim.x + threadIdx.x;
    unsigned stride = gridDim.x * blockDim.x;
    for (unsigned i = tid; i < 4096u; i += stride) { g_coarse[i] = 0u; g_fine[i] = 0u; g_lowh[i] = 0u; }
    for (unsigned i = tid; i < 2048u; i += stride) g_whist[i] = 0u;
    if (tid == 0) {
        g_below = 0u; g_done1 = 0u; g_done2 = 0u; g_d2 = 0u;
        g_s2r = 0u; g_rdy2 = 0u; g_ovf = 0u;
    }
}

// ---------------------------------------------------------------------------
// Persistent 2-phase sampling kernel. 264 blocks (all resident).
__global__ void __launch_bounds__(NTHREADS, 2)
sample_kernel(const float* __restrict__ xs,
              const float* __restrict__ ms,
              const int* __restrict__ t_ptr,
              const float* __restrict__ sparsity,
              unsigned n) {
    __shared__ unsigned sh[4096];
    __shared__ unsigned sscan[256];
    __shared__ unsigned svlo, svhi, svS;
    for (unsigned i = threadIdx.x; i < 4096u; i += blockDim.x) sh[i] = 0u;
    __syncthreads();

    float tf = read_tf(t_ptr);
    unsigned n4 = n >> 2;
    unsigned nsamp4 = NCHUNKS * CHUNK_F4;
    bool small = (n4 < nsamp4);
    const float4* x4 = (const float4*)xs;
    const float4* m4 = (const float4*)ms;
    unsigned gstride = gridDim.x * blockDim.x;
    int t = threadIdx.x;
    if (small) nsamp4 = n4;

    // ---- phase 1: coarse hist (top 12 bits) ----
    for (unsigned i = blockIdx.x * blockDim.x + t; i < nsamp4; i += gstride) {
        unsigned idx;
        if (small) idx = i;
        else {
            unsigned chunk = i >> 7;
            unsigned off   = i & (CHUNK_F4 - 1u);
            idx = (unsigned)(((unsigned long long)chunk * n4) / NCHUNKS) + off;
        }
        float4 xv = x4[idx];
        float4 mv = m4[idx];
        agg_shared_add(sh, key_of(xv.x, mv.x, tf) >> 20);
        agg_shared_add(sh, key_of(xv.y, mv.y, tf) >> 20);
        agg_shared_add(sh, key_of(xv.z, mv.z, tf) >> 20);
        agg_shared_add(sh, key_of(xv.w, mv.w, tf) >> 20);
    }
    __syncthreads();
    for (unsigned i = t; i < 4096u; i += blockDim.x) {
        unsigned c = sh[i];
        if (c) atomicAdd(&g_coarse[i], c);
    }
    __threadfence();

    __shared__ unsigned slast;
    if (t == 0)
        slast = (atomicAdd(&g_done1, 1u) == gridDim.x - 1u) ? 1u : 0u;
    __syncthreads();

    unsigned R = rank_R(sparsity, n);

    if (slast) {
        unsigned loc[16];
        unsigned lsum = 0u;
        #pragma unroll
        for (int j = 0; j < 16; j++) { loc[j] = g_coarse[t * 16 + j]; lsum += loc[j]; }
        sscan[t] = lsum;
        __syncthreads();
        for (int off = 1; off < 256; off <<= 1) {
            unsigned v = (t >= off) ? sscan[t - off] : 0u;
            __syncthreads();
            sscan[t] += v;
            __syncthreads();
        }
        unsigned incl  = sscan[t];
        unsigned total = sscan[255];
        unsigned before = incl - lsum;

        float f = (float)R / (float)n;
        float tlo = (f - 0.003f) * (float)total;
        float thi = (f + 0.003f) * (float)total + 1.0f;
        unsigned slo = (tlo < 1.0f) ? 1u : (unsigned)tlo;
        if (slo > total) slo = total;
        unsigned shi = (thi < 1.0f) ? 1u : (unsigned)thi;
        if (shi > total) shi = total;
        if (shi < slo) shi = slo;

        if (slo > before && slo <= incl) {
            unsigned run = before;
            #pragma unroll
            for (int j = 0; j < 16; j++) {
                if (slo <= run + loc[j]) { svlo = (unsigned)(t * 16 + j); svS = run; break; }
                run += loc[j];
            }
        }
        if (shi > before && shi <= incl) {
            unsigned run = before;
            #pragma unroll
            for (int j = 0; j < 16; j++) {
                if (shi <= run + loc[j]) { svhi = (unsigned)(t * 16 + j); break; }
                run += loc[j];
            }
        }
        __syncthreads();
        if (t == 0) {
            unsigned blo = svlo, bhi = svhi;
            if (bhi < blo) bhi = blo;
            if (bhi - blo + 1u > 16u) bhi = blo + 15u;
            unsigned span = bhi - blo + 1u;
            unsigned fs = 8u;
            while ((((unsigned long long)span << 20) >> fs) > 4096ull) fs++;
            g_wbase = blo << 20;
            g_fs = fs;
            g_tlo = slo - svS;
            g_thi = (shi > svS) ? (shi - svS) : 1u;
            __threadfence();
            atomicExch(&g_s2r, 1u);
        }
    }

    // ---- phase 2: fine hist over window (samples L2-hot) ----
    if (t == 0) { while (atomicAdd(&g_s2r, 0u) == 0u) {} }
    __syncthreads();
    unsigned wbase = g_wbase;
    unsigned fs    = g_fs;

    for (unsigned i = t; i < 4096u; i += blockDim.x) sh[i] = 0u;
    __syncthreads();
    for (unsigned i = blockIdx.x * blockDim.x + t; i < nsamp4; i += gstride) {
        unsigned idx;
        if (small) idx = i;
        else {
            unsigned chunk = i >> 7;
            unsigned off   = i & (CHUNK_F4 - 1u);
            idx = (unsigned)(((unsigned long long)chunk * n4) / NCHUNKS) + off;
        }
        float4 xv = x4[idx];
        float4 mv = m4[idx];
        unsigned kk[4];
        kk[0] = key_of(xv.x, mv.x, tf);
        kk[1] = key_of(xv.y, mv.y, tf);
        kk[2] = key_of(xv.z, mv.z, tf);
        kk[3] = key_of(xv.w, mv.w, tf);
        #pragma unroll
        for (int j = 0; j < 4; j++) {
            if (kk[j] >= wbase) {
                unsigned b = (kk[j] - wbase) >> fs;
                if (b < 4096u) agg_shared_add(sh, b);
            }
        }
    }
    __syncthreads();
    for (unsigned i = t; i < 4096u; i += blockDim.x) {
        unsigned c = sh[i];
        if (c) atomicAdd(&g_fine[i], c);
    }
    __threadfence();

    __shared__ unsigned slast2;
    if (t == 0)
        slast2 = (atomicAdd(&g_done2, 1u) == gridDim.x - 1u) ? 1u : 0u;
    __syncthreads();
    if (!slast2) return;

    // ---- last block: fine window -> exact key bounds ----
    {
        unsigned loc[16];
        unsigned lsum = 0u;
        #pragma unroll
        for (int j = 0; j < 16; j++) { loc[j] = g_fine[t * 16 + j]; lsum += loc[j]; }
        sscan[t] = lsum;
        __syncthreads();
        for (int off = 1; off < 256; off <<= 1) {
            unsigned v = (t >= off) ? sscan[t - off] : 0u;
            __syncthreads();
            sscan[t] += v;
            __syncthreads();
        }
        unsigned incl  = sscan[t];
        unsigned total = sscan[255];
        unsigned before = incl - lsum;

        if (t == 0) { svlo = 0u; svhi = 2047u; }
        __syncthreads();

        if (total > 0u) {
            unsigned tl = g_tlo; if (tl < 1u) tl = 1u; if (tl > total) tl = total;
            unsigned th = g_thi; if (th < tl) th = tl; if (th > total) th = total;
            if (tl > before && tl <= incl) {
                unsigned run = before;
                #pragma unroll
                for (int j = 0; j < 16; j++) {
                    if (tl <= run + loc[j]) { svlo = (unsigned)(t * 16 + j); break; }
                    run += loc[j];
                }
            }
            if (th > before && th <= incl) {
                unsigned run = before;
                #pragma unroll
                for (int j = 0; j < 16; j++) {
                    if (th <= run + loc[j]) { svhi = (unsigned)(t * 16 + j); break; }
                    run += loc[j];
                }
            }
        }
        __syncthreads();
        if (t == 0) {
            unsigned flo = svlo, fhi = svhi;
            if (fhi < flo) fhi = flo;
            if (fhi - flo > 2047u) fhi = flo + 2047u;
            g_klo = wbase + (flo << fs);
            g_khi = wbase + ((fhi + 1u) << fs);
        }
    }
}

// ---------------------------------------------------------------------------
// Single fused streaming pass: no tiles, no mainloop barriers, MLP-8 loads,
// warp-ballot direct candidate compaction.
__global__ void __launch_bounds__(NTHREADS, 8)
passA_kernel(const float* __restrict__ xs,
             const float* __restrict__ ms,
             const int* __restrict__ t_ptr,
             float* __restrict__ out,
             unsigned n) {
    __shared__ unsigned s_whist[2048];
    __shared__ unsigned s_cnt;
    __shared__ unsigned s_red[NTHREADS];

    for (unsigned i = threadIdx.x; i < 2048u; i += blockDim.x) s_whist[i] = 0u;
    if (threadIdx.x == 0) s_cnt = 0u;
    __syncthreads();

    float tf = read_tf(t_ptr);
    unsigned k_lo = g_klo, k_hi = g_khi;
    unsigned fs = g_fs;
    unsigned n4 = n >> 2;
    const float4* x4 = (const float4*)xs;
    const float4* m4 = (const float4*)ms;
    float4* o4 = (float4*)out;

    unsigned region = blockIdx.x * PER_BLOCK;
    unsigned below = 0u;
    unsigned lane = threadIdx.x & 31u;
    unsigned tile = NTHREADS * 4u;

    for (unsigned tb = blockIdx.x * tile; tb < n4; tb += gridDim.x * tile) {
        float4 xv[4], mv[4];
        unsigned id[4];
        bool ok[4];
        #pragma unroll
        for (int k = 0; k < 4; k++) {
            id[k] = tb + (unsigned)k * NTHREADS + threadIdx.x;
            ok[k] = id[k] < n4;
            if (ok[k]) { xv[k] = __ldcs(&x4[id[k]]); mv[k] = __ldcs(&m4[id[k]]); }
        }
        #pragma unroll
        for (int k = 0; k < 4; k++) {
            if (ok[k]) {
                unsigned kk[4];
                kk[0] = key_of(xv[k].x, mv[k].x, tf);
                kk[1] = key_of(xv[k].y, mv[k].y, tf);
                kk[2] = key_of(xv[k].z, mv[k].z, tf);
                kk[3] = key_of(xv[k].w, mv[k].w, tf);
                float vv[4] = {xv[k].x, xv[k].y, xv[k].z, xv[k].w};
                float ov[4];
                #pragma unroll
                for (int j = 0; j < 4; j++) {
                    below += (kk[j] < k_lo) ? 1u : 0u;
                    ov[j] = (kk[j] >= k_hi) ? vv[j] : 0.0f;
                }
                __stcs(&o4[id[k]], make_float4(ov[0], ov[1], ov[2], ov[3]));
                #pragma unroll
                for (int j = 0; j < 4; j++) {
                    bool cand = (kk[j] >= k_lo) && (kk[j] < k_hi);
                    unsigned act  = __activemask();
                    unsigned ball = __ballot_sync(act, cand);
                    if (ball) {
                        int leader = __ffs(ball) - 1;
                        unsigned base = 0u;
                        if ((int)lane == leader)
                            base = atomicAdd(&s_cnt, (unsigned)__popc(ball));
                        base = __shfl_sync(act, base, leader);
                        if (cand) {
                            unsigned pos = base + (unsigned)__popc(ball & ((1u << lane) - 1u));
                            if (pos < PER_BLOCK)
                                g_cand[region + pos] = make_uint2(kk[j], id[k] * 4u + (unsigned)j);
                            atomicAdd(&s_whist[(kk[j] - k_lo) >> fs], 1u);
                        }
                    }
                }
            }
        }
    }

    // scalar tail (n % 4)
    if (blockIdx.x == 0 && threadIdx.x == 0) {
        for (unsigned i = n4 << 2; i < n; i++) {
            unsigned key = key_of(xs[i], ms[i], tf);
            below += (key < k_lo) ? 1u : 0u;
            out[i] = (key >= k_hi) ? xs[i] : 0.0f;
            if (key >= k_lo && key < k_hi) {
                unsigned pos = atomicAdd(&s_cnt, 1u);
                if (pos < PER_BLOCK)
                    g_cand[region + pos] = make_uint2(key, i);
                atomicAdd(&s_whist[(key - k_lo) >> fs], 1u);
            }
        }
    }
    __syncthreads();

    if (threadIdx.x == 0) {
        unsigned cnt = s_cnt;
        if (cnt > PER_BLOCK) { atomicExch(&g_ovf, 1u); cnt = PER_BLOCK; }
        g_blk_cnt[blockIdx.x] = cnt;
    }

    s_red[threadIdx.x] = below;
    __syncthreads();
    for (int off = NTHREADS / 2; off > 0; off >>= 1) {
        if ((int)threadIdx.x < off) s_red[threadIdx.x] += s_red[threadIdx.x + off];
        __syncthreads();
    }
    if (threadIdx.x == 0 && s_red[0]) atomicAdd(&g_below, s_red[0]);

    for (unsigned i = threadIdx.x; i < 2048u; i += blockDim.x) {
        unsigned c = s_whist[i];
        if (c) atomicAdd(&g_whist[i], c);
    }
}

// ---------------------------------------------------------------------------
// Persistent tail: one unrolled region stream + one grid barrier.
__global__ void __launch_bounds__(NTHREADS, 8)
resolve_kernel(const float* __restrict__ xs,
               const float* __restrict__ ms,
               const int* __restrict__ t_ptr,
               const float* __restrict__ sparsity,
               float* __restrict__ out,
               unsigned n) {
    __shared__ unsigned ss[NTHREADS];
    __shared__ unsigned sh[4096];
    __shared__ uint2    stash[STASH_MAX];
    __shared__ unsigned sb1, sr1, s_stash;
    __shared__ unsigned sv[4];
    int t = threadIdx.x;

    // ---- select fine bin b1 + r1 from g_whist + g_below ----
    if (t == 0) { sb1 = 0xFFFFFFFFu; sr1 = 1u; s_stash = 0u; }
    unsigned c[8];
    unsigned local = 0u;
    #pragma unroll
    for (int j = 0; j < 8; j++) { c[j] = g_whist[t * 8 + j]; local += c[j]; }
    ss[t] = local;
    __syncthreads();
    for (int off = 1; off < NTHREADS; off <<= 1) {
        unsigned v = (t >= off) ? ss[t - off] : 0u;
        __syncthreads();
        ss[t] += v;
        __syncthreads();
    }
    unsigned incl   = ss[t];
    unsigned total  = ss[NTHREADS - 1];
    unsigned before = incl - local;

    unsigned below = g_below;
    unsigned R = rank_R(sparsity, n);
    bool fb = (below >= R) || ((R - below) > total) || (g_ovf != 0u);
    unsigned Rp = R - below;

    if (!fb && Rp > before && Rp <= incl) {
        unsigned run = before;
        #pragma unroll
        for (int j = 0; j < 8; j++) {
            if (Rp <= run + c[j]) {
                sb1 = (unsigned)(t * 8 + j);
                sr1 = Rp - run;
                break;
            }
            run += c[j];
        }
    }
    __syncthreads();

    // ---- fallback: block 0 exact 3-level radix over full data ----
    if (fb) {
        if (blockIdx.x != 0) return;
        float tf = read_tf(t_ptr);

        for (unsigned i = t; i < 4096u; i += blockDim.x) sh[i] = 0u;
        __syncthreads();
        for (unsigned i = t; i < n; i += blockDim.x)
            atomicAdd(&sh[key_of(xs[i], ms[i], tf) >> 20], 1u);
        __syncthreads();
        if (t == 0) {
            unsigned run = 0u;
            for (unsigned b = 0; b < 4096u; b++) {
                if (R <= run + sh[b]) { sv[0] = b; sv[1] = R - run; break; }
                run += sh[b];
            }
        }
        __syncthreads();
        unsigned b1 = sv[0], r1 = sv[1];

        for (unsigned i = t; i < 1024u; i += blockDim.x) sh[i] = 0u;
        __syncthreads();
        for (unsigned i = t; i < n; i += blockDim.x) {
            unsigned k = key_of(xs[i], ms[i], tf);
            if ((k >> 20) == b1) atomicAdd(&sh[(k >> 10) & 1023u], 1u);
        }
        __syncthreads();
        if (t == 0) {
            unsigned run = 0u;
            for (unsigned b = 0; b < 1024u; b++) {
                if (r1 <= run + sh[b]) { sv[2] = b; sv[1] = r1 - run; break; }
                run += sh[b];
            }
        }
        __syncthreads();
        unsigned b2 = sv[2], r2 = sv[1];
        unsigned pre = (b1 << 10) | b2;

        for (unsigned i = t; i < 1024u; i += blockDim.x) sh[i] = 0u;
        __syncthreads();
        for (unsigned i = t; i < n; i += blockDim.x) {
            unsigned k = key_of(xs[i], ms[i], tf);
            if ((k >> 10) == pre) atomicAdd(&sh[k & 1023u], 1u);
        }
        __syncthreads();
        if (t == 0) {
            unsigned run = 0u;
            for (unsigned b = 0; b < 1024u; b++) {
                if (r2 <= run + sh[b]) { sv[3] = (pre << 10) | b; break; }
                run += sh[b];
            }
        }
        __syncthreads();
        unsigned thr = sv[3];
        for (unsigned i = t; i < n; i += blockDim.x) {
            unsigned k = key_of(xs[i], ms[i], tf);
            out[i] = (k >= thr) ? xs[i] : 0.0f;
        }
        return;
    }

    unsigned b1 = sb1;
    unsigned r1 = sr1;
    unsigned k_lo = g_klo;
    unsigned fs   = g_fs;
    unsigned nlow = 1u << fs;
    unsigned b1start = k_lo + (b1 << fs);
    unsigned b1end   = b1start + (1u << fs);
    unsigned lowmask = nlow - 1u;
    unsigned cnt    = g_blk_cnt[blockIdx.x];
    unsigned region = blockIdx.x * PER_BLOCK;

    // ---- phase A: single region stream, unrolled x4 for MLP ----
    for (unsigned i = t; i < nlow; i += blockDim.x) sh[i] = 0u;
    __syncthreads();

    unsigned j = (unsigned)t;
    for (; j + 3u * NTHREADS < cnt; j += 4u * NTHREADS) {
        uint2 r0 = g_cand[region + j];
        uint2 r1v = g_cand[region + j + NTHREADS];
        uint2 r2 = g_cand[region + j + 2u * NTHREADS];
        uint2 r3 = g_cand[region + j + 3u * NTHREADS];
        uint2 rr[4] = {r0, r1v, r2, r3};
        #pragma unroll
        for (int q = 0; q < 4; q++) {
            uint2 r = rr[q];
            if (r.x >= b1end) out[r.y] = xs[r.y];
            else if (r.x >= b1start) {
                agg_shared_add(sh, r.x & lowmask);
                unsigned pos = atomicAdd(&s_stash, 1u);
                if (pos < STASH_MAX) stash[pos] = r;
            }
        }
    }
    for (; j < cnt; j += NTHREADS) {
        uint2 r = g_cand[region + j];
        if (r.x >= b1end) out[r.y] = xs[r.y];
        else if (r.x >= b1start) {
            agg_shared_add(sh, r.x & lowmask);
            unsigned pos = atomicAdd(&s_stash, 1u);
            if (pos < STASH_MAX) stash[pos] = r;
        }
    }
    __syncthreads();
    for (unsigned i = t; i < nlow; i += blockDim.x) {
        unsigned h = sh[i];
        if (h) atomicAdd(&g_lowh[i], h);
    }
    __threadfence();
    __syncthreads();
    if (t == 0) atomicAdd(&g_d2, 1u);

    // ---- block 0: exact threshold from low hist ----
    if (blockIdx.x == 0) {
        if (t == 0) { while (atomicAdd(&g_d2, 0u) < gridDim.x) {} }
        __syncthreads();
        unsigned q[16];
        unsigned loc = 0u;
        #pragma unroll
        for (int jj = 0; jj < 16; jj++) { q[jj] = g_lowh[t * 16 + jj]; loc += q[jj]; }
        ss[t] = loc;
        __syncthreads();
        for (int off = 1; off < NTHREADS; off <<= 1) {
            unsigned v = (t >= off) ? ss[t - off] : 0u;
            __syncthreads();
            ss[t] += v;
            __syncthreads();
        }
        unsigned inc3 = ss[t];
        unsigned bef3 = inc3 - loc;
        if (r1 > bef3 && r1 <= inc3) {
            unsigned run = bef3;
            #pragma unroll
            for (int jj = 0; jj < 16; jj++) {
                if (r1 <= run + q[jj]) {
                    g_thr_key = b1start + (unsigned)(t * 16 + jj);
                    break;
                }
                run += q[jj];
            }
        }
        __syncthreads();
        if (t == 0) { __threadfence(); atomicExch(&g_rdy2, 1u); }
    }

    // ---- apply thr to stashed b1 cands ----
    if (t == 0) { while (atomicAdd(&g_rdy2, 0u) == 0u) {} }
    __syncthreads();
    unsigned thr = g_thr_key;
    unsigned nst = s_stash;
    if (nst <= STASH_MAX) {
        for (unsigned jj = (unsigned)t; jj < nst; jj += blockDim.x) {
            uint2 r = stash[jj];
            if (r.x >= thr) out[r.y] = xs[r.y];
        }
    } else {
        for (unsigned jj = (unsigned)t; jj < cnt; jj += blockDim.x) {
            uint2 r = g_cand[region + jj];
            if (r.x >= thr && r.x < b1end) out[r.y] = xs[r.y];
        }
    }
}

// ---------------------------------------------------------------------------
extern "C" void kernel_launch(void* const* d_in, const int* in_sizes, int n_in,
                              void* d_out, int out_size) {
    const float* xs = (const float*)d_in[0];
    const float* ms = (const float*)d_in[1];
    const float* sp = (const float*)d_in[2];
    // d_in[3] = mask (unused by the reference computation)
    const int* t_ptr = (n_in >= 5) ? (const int*)d_in[4] : nullptr;

    unsigned n = (unsigned)in_sizes[0];
    float* out = (float*)d_out;

    zero_kernel<<<4, 1024>>>();
    sample_kernel<<<264, 256>>>(xs, ms, t_ptr, sp, n);
    passA_kernel<<<NBLOCKS, NTHREADS>>>(xs, ms, t_ptr, out, n);
    resolve_kernel<<<NBLOCKS, NTHREADS>>>(xs, ms, t_ptr, sp, out, n);
}

// round 11
// speedup vs baseline: 1.1429x; 1.1429x over previous
#include <cuda_runtime.h>
#include <stdint.h>

// ---------------------------------------------------------------------------
// MagnitudePruning via 2-level-sampled key-window radix select on
// s = t*magnitude + |x|  (monotone surrogate; uniform divide preserves rank).
//
// zero    : clear small histograms/counters
// sample  : persistent 2-phase, chunked coalesced sampling (1M samples):
//           coarse 4096-bin hist -> coarse window -> runtime shift fs ->
//           fine 4096-bin hist (samples L2-hot) -> key window [k_lo,k_hi)
// passA   : ONE full fused pass (tiled shared staging, MLP-4 batched loads):
//           exact below-count, final out for out-of-window, compact window
//           cands to per-block regions, 2048-bin fine whist
// resolve : persistent: select fine bin b1+r1; ONE region stream (finalize
//           key>=b1_end, stash+low-hist b1 cands); block0 -> exact thr;
//           apply from stash. Exact single-block fallback on any miss.
// ---------------------------------------------------------------------------

#define NBLOCKS    1184u
#define NTHREADS   256u
#define TILE_F4    512u
#define PER_BLOCK  40960u
#define STASH_MAX  512u
#define NCHUNKS    2048u
#define CHUNK_F4   128u

__device__ unsigned g_coarse[4096];
__device__ unsigned g_fine[4096];
__device__ unsigned g_whist[2048];
__device__ unsigned g_lowh[4096];
__device__ unsigned g_below;
__device__ unsigned g_done1, g_done2, g_d2;
__device__ unsigned g_s2r, g_rdy2;
__device__ unsigned g_ovf;
__device__ unsigned g_wbase, g_fs, g_tlo, g_thi;
__device__ unsigned g_klo, g_khi;
__device__ unsigned g_thr_key;
__device__ unsigned g_blk_cnt[NBLOCKS];
__device__ uint2    g_cand[NBLOCKS * PER_BLOCK];

__device__ __forceinline__ unsigned key_of(float x, float m, float tf) {
    float s = __fadd_rn(__fmul_rn(tf, m), fabsf(x));
    return __float_as_uint(s);
}
__device__ __forceinline__ float read_tf(const int* t_ptr) {
    return t_ptr ? (float)(*t_ptr) : 1.0f;
}
__device__ __forceinline__ unsigned rank_R(const float* sp, unsigned n) {
    float fidx = floorf(__fsub_rn(__fmul_rn(sp[0], (float)n), 1.0f));
    long long idx = (long long)fidx;
    if (idx < 0) idx = 0;
    if (idx > (long long)(n - 1)) idx = (long long)(n - 1);
    return (unsigned)idx + 1u;
}
__device__ __forceinline__ void agg_shared_add(unsigned* hist, unsigned bin) {
    unsigned act    = __activemask();
    unsigned peers  = __match_any_sync(act, bin);
    int      leader = __ffs(peers) - 1;
    if ((int)(threadIdx.x & 31) == leader)
        atomicAdd(&hist[bin], (unsigned)__popc(peers));
}

// ---------------------------------------------------------------------------
__global__ void zero_kernel() {
    unsigned tid = blockIdx.x * blockDim.x + threadIdx.x;
    unsigned stride = gridDim.x * blockDim.x;
    for (unsigned i = tid; i < 4096u; i += stride) { g_coarse[i] = 0u; g_fine[i] = 0u; g_lowh[i] = 0u; }
    for (unsigned i = tid; i < 2048u; i += stride) g_whist[i] = 0u;
    if (tid == 0) {
        g_below = 0u; g_done1 = 0u; g_done2 = 0u; g_d2 = 0u;
        g_s2r = 0u; g_rdy2 = 0u; g_ovf = 0u;
    }
}

// ---------------------------------------------------------------------------
// Persistent 2-phase sampling kernel. 264 blocks (all resident).
__global__ void __launch_bounds__(NTHREADS, 2)
sample_kernel(const float* __restrict__ xs,
              const float* __restrict__ ms,
              const int* __restrict__ t_ptr,
              const float* __restrict__ sparsity,
              unsigned n) {
    __shared__ unsigned sh[4096];
    __shared__ unsigned sscan[256];
    __shared__ unsigned svlo, svhi, svS;
    for (unsigned i = threadIdx.x; i < 4096u; i += blockDim.x) sh[i] = 0u;
    __syncthreads();

    float tf = read_tf(t_ptr);
    unsigned n4 = n >> 2;
    unsigned nsamp4 = NCHUNKS * CHUNK_F4;
    bool small = (n4 < nsamp4);
    const float4* x4 = (const float4*)xs;
    const float4* m4 = (const float4*)ms;
    unsigned gstride = gridDim.x * blockDim.x;
    int t = threadIdx.x;
    if (small) nsamp4 = n4;

    // ---- phase 1: coarse hist (top 12 bits) ----
    for (unsigned i = blockIdx.x * blockDim.x + t; i < nsamp4; i += gstride) {
        unsigned idx;
        if (small) idx = i;
        else {
            unsigned chunk = i >> 7;
            unsigned off   = i & (CHUNK_F4 - 1u);
            idx = (unsigned)(((unsigned long long)chunk * n4) / NCHUNKS) + off;
        }
        float4 xv = x4[idx];
        float4 mv = m4[idx];
        agg_shared_add(sh, key_of(xv.x, mv.x, tf) >> 20);
        agg_shared_add(sh, key_of(xv.y, mv.y, tf) >> 20);
        agg_shared_add(sh, key_of(xv.z, mv.z, tf) >> 20);
        agg_shared_add(sh, key_of(xv.w, mv.w, tf) >> 20);
    }
    __syncthreads();
    for (unsigned i = t; i < 4096u; i += blockDim.x) {
        unsigned c = sh[i];
        if (c) atomicAdd(&g_coarse[i], c);
    }
    __threadfence();

    __shared__ unsigned slast;
    if (t == 0)
        slast = (atomicAdd(&g_done1, 1u) == gridDim.x - 1u) ? 1u : 0u;
    __syncthreads();

    unsigned R = rank_R(sparsity, n);

    if (slast) {
        unsigned loc[16];
        unsigned lsum = 0u;
        #pragma unroll
        for (int j = 0; j < 16; j++) { loc[j] = g_coarse[t * 16 + j]; lsum += loc[j]; }
        sscan[t] = lsum;
        __syncthreads();
        for (int off = 1; off < 256; off <<= 1) {
            unsigned v = (t >= off) ? sscan[t - off] : 0u;
            __syncthreads();
            sscan[t] += v;
            __syncthreads();
        }
        unsigned incl  = sscan[t];
        unsigned total = sscan[255];
        unsigned before = incl - lsum;

        float f = (float)R / (float)n;
        float tlo = (f - 0.003f) * (float)total;
        float thi = (f + 0.003f) * (float)total + 1.0f;
        unsigned slo = (tlo < 1.0f) ? 1u : (unsigned)tlo;
        if (slo > total) slo = total;
        unsigned shi = (thi < 1.0f) ? 1u : (unsigned)thi;
        if (shi > total) shi = total;
        if (shi < slo) shi = slo;

        if (slo > before && slo <= incl) {
            unsigned run = before;
            #pragma unroll
            for (int j = 0; j < 16; j++) {
                if (slo <= run + loc[j]) { svlo = (unsigned)(t * 16 + j); svS = run; break; }
                run += loc[j];
            }
        }
        if (shi > before && shi <= incl) {
            unsigned run = before;
            #pragma unroll
            for (int j = 0; j < 16; j++) {
                if (shi <= run + loc[j]) { svhi = (unsigned)(t * 16 + j); break; }
                run += loc[j];
            }
        }
        __syncthreads();
        if (t == 0) {
            unsigned blo = svlo, bhi = svhi;
            if (bhi < blo) bhi = blo;
            if (bhi - blo + 1u > 16u) bhi = blo + 15u;
            unsigned span = bhi - blo + 1u;
            unsigned fs = 8u;
            while ((((unsigned long long)span << 20) >> fs) > 4096ull) fs++;
            g_wbase = blo << 20;
            g_fs = fs;
            g_tlo = slo - svS;
            g_thi = (shi > svS) ? (shi - svS) : 1u;
            __threadfence();
            atomicExch(&g_s2r, 1u);
        }
    }

    // ---- phase 2: fine hist over window (samples L2-hot) ----
    if (t == 0) { while (atomicAdd(&g_s2r, 0u) == 0u) {} }
    __syncthreads();
    unsigned wbase = g_wbase;
    unsigned fs    = g_fs;

    for (unsigned i = t; i < 4096u; i += blockDim.x) sh[i] = 0u;
    __syncthreads();
    for (unsigned i = blockIdx.x * blockDim.x + t; i < nsamp4; i += gstride) {
        unsigned idx;
        if (small) idx = i;
        else {
            unsigned chunk = i >> 7;
            unsigned off   = i & (CHUNK_F4 - 1u);
            idx = (unsigned)(((unsigned long long)chunk * n4) / NCHUNKS) + off;
        }
        float4 xv = x4[idx];
        float4 mv = m4[idx];
        unsigned kk[4];
        kk[0] = key_of(xv.x, mv.x, tf);
        kk[1] = key_of(xv.y, mv.y, tf);
        kk[2] = key_of(xv.z, mv.z, tf);
        kk[3] = key_of(xv.w, mv.w, tf);
        #pragma unroll
        for (int j = 0; j < 4; j++) {
            if (kk[j] >= wbase) {
                unsigned b = (kk[j] - wbase) >> fs;
                if (b < 4096u) agg_shared_add(sh, b);
            }
        }
    }
    __syncthreads();
    for (unsigned i = t; i < 4096u; i += blockDim.x) {
        unsigned c = sh[i];
        if (c) atomicAdd(&g_fine[i], c);
    }
    __threadfence();

    __shared__ unsigned slast2;
    if (t == 0)
        slast2 = (atomicAdd(&g_done2, 1u) == gridDim.x - 1u) ? 1u : 0u;
    __syncthreads();
    if (!slast2) return;

    // ---- last block: fine window -> exact key bounds ----
    {
        unsigned loc[16];
        unsigned lsum = 0u;
        #pragma unroll
        for (int j = 0; j < 16; j++) { loc[j] = g_fine[t * 16 + j]; lsum += loc[j]; }
        sscan[t] = lsum;
        __syncthreads();
        for (int off = 1; off < 256; off <<= 1) {
            unsigned v = (t >= off) ? sscan[t - off] : 0u;
            __syncthreads();
            sscan[t] += v;
            __syncthreads();
        }
        unsigned incl  = sscan[t];
        unsigned total = sscan[255];
        unsigned before = incl - lsum;

        if (t == 0) { svlo = 0u; svhi = 2047u; }
        __syncthreads();

        if (total > 0u) {
            unsigned tl = g_tlo; if (tl < 1u) tl = 1u; if (tl > total) tl = total;
            unsigned th = g_thi; if (th < tl) th = tl; if (th > total) th = total;
            if (tl > before && tl <= incl) {
                unsigned run = before;
                #pragma unroll
                for (int j = 0; j < 16; j++) {
                    if (tl <= run + loc[j]) { svlo = (unsigned)(t * 16 + j); break; }
                    run += loc[j];
                }
            }
            if (th > before && th <= incl) {
                unsigned run = before;
                #pragma unroll
                for (int j = 0; j < 16; j++) {
                    if (th <= run + loc[j]) { svhi = (unsigned)(t * 16 + j); break; }
                    run += loc[j];
                }
            }
        }
        __syncthreads();
        if (t == 0) {
            unsigned flo = svlo, fhi = svhi;
            if (fhi < flo) fhi = flo;
            if (fhi - flo > 2047u) fhi = flo + 2047u;
            g_klo = wbase + (flo << fs);
            g_khi = wbase + ((fhi + 1u) << fs);
        }
    }
}

// ---------------------------------------------------------------------------
// Process one float4 pair: decide/store out, stage candidates in shared.
__device__ __forceinline__ void passA_process(
    float4 xv, float4 mv, unsigned i, float tf,
    unsigned k_lo, unsigned k_hi, unsigned fs,
    float4* o4, uint2* s_buf, unsigned* s_cnt, unsigned* s_whist,
    unsigned& below) {
    unsigned kk[4];
    kk[0] = key_of(xv.x, mv.x, tf);
    kk[1] = key_of(xv.y, mv.y, tf);
    kk[2] = key_of(xv.z, mv.z, tf);
    kk[3] = key_of(xv.w, mv.w, tf);
    float vv[4] = {xv.x, xv.y, xv.z, xv.w};
    float ov[4];
    unsigned e = i * 4u;
    #pragma unroll
    for (int j = 0; j < 4; j++) {
        unsigned key = kk[j];
        below += (key < k_lo) ? 1u : 0u;
        ov[j] = (key >= k_hi) ? vv[j] : 0.0f;
        if (key >= k_lo && key < k_hi) {
            unsigned pos = atomicAdd(s_cnt, 1u);
            s_buf[pos] = make_uint2(key, e + (unsigned)j);
            agg_shared_add(s_whist, (key - k_lo) >> fs);
        }
    }
    __stcs(&o4[i], make_float4(ov[0], ov[1], ov[2], ov[3]));
}

// The single fused full pass over all data (MLP-4 batched streaming loads).
__global__ void __launch_bounds__(NTHREADS, 8)
passA_kernel(const float* __restrict__ xs,
             const float* __restrict__ ms,
             const int* __restrict__ t_ptr,
             float* __restrict__ out,
             unsigned n) {
    __shared__ uint2    s_buf[2048];
    __shared__ unsigned s_whist[2048];
    __shared__ unsigned s_cnt;
    __shared__ unsigned s_red[NTHREADS];

    for (unsigned i = threadIdx.x; i < 2048u; i += blockDim.x) s_whist[i] = 0u;

    float tf = read_tf(t_ptr);
    unsigned k_lo = g_klo, k_hi = g_khi;
    unsigned fs = g_fs;
    unsigned n4 = n >> 2;
    const float4* x4 = (const float4*)xs;
    const float4* m4 = (const float4*)ms;
    float4* o4 = (float4*)out;

    unsigned region = blockIdx.x * PER_BLOCK;
    unsigned nreg = 0u;
    unsigned below = 0u;
    unsigned ntiles = (n4 + TILE_F4 - 1u) / TILE_F4;

    for (unsigned tile = blockIdx.x; tile < ntiles; tile += gridDim.x) {
        if (threadIdx.x == 0) s_cnt = 0u;
        __syncthreads();

        unsigned tbase = tile * TILE_F4;
        unsigned i0 = tbase + threadIdx.x;
        unsigned i1 = i0 + NTHREADS;
        bool ok0 = i0 < n4, ok1 = i1 < n4;
        float4 xv0, mv0, xv1, mv1;
        // front-batched loads: MLP 4
        if (ok0) { xv0 = __ldcs(&x4[i0]); mv0 = __ldcs(&m4[i0]); }
        if (ok1) { xv1 = __ldcs(&x4[i1]); mv1 = __ldcs(&m4[i1]); }
        if (ok0) passA_process(xv0, mv0, i0, tf, k_lo, k_hi, fs, o4, s_buf, &s_cnt, s_whist, below);
        if (ok1) passA_process(xv1, mv1, i1, tf, k_lo, k_hi, fs, o4, s_buf, &s_cnt, s_whist, below);
        __syncthreads();

        unsigned cnt = s_cnt;
        if (cnt) {
            if (nreg + cnt <= PER_BLOCK) {
                for (unsigned j = threadIdx.x; j < cnt; j += blockDim.x)
                    g_cand[region + nreg + j] = s_buf[j];
                nreg += cnt;
            } else {
                if (threadIdx.x == 0) atomicExch(&g_ovf, 1u);
            }
        }
        __syncthreads();
    }

    // scalar tail (n % 4)
    if (blockIdx.x == 0 && threadIdx.x == 0) {
        for (unsigned i = n4 << 2; i < n; i++) {
            unsigned key = key_of(xs[i], ms[i], tf);
            below += (key < k_lo) ? 1u : 0u;
            out[i] = (key >= k_hi) ? xs[i] : 0.0f;
            if (key >= k_lo && key < k_hi) {
                if (nreg < PER_BLOCK) {
                    g_cand[region + nreg] = make_uint2(key, i);
                    nreg++;
                    atomicAdd(&s_whist[(key - k_lo) >> fs], 1u);
                } else {
                    atomicExch(&g_ovf, 1u);
                }
            }
        }
    }
    __syncthreads();

    if (threadIdx.x == 0) g_blk_cnt[blockIdx.x] = nreg;

    s_red[threadIdx.x] = below;
    __syncthreads();
    for (int off = NTHREADS / 2; off > 0; off >>= 1) {
        if ((int)threadIdx.x < off) s_red[threadIdx.x] += s_red[threadIdx.x + off];
        __syncthreads();
    }
    if (threadIdx.x == 0 && s_red[0]) atomicAdd(&g_below, s_red[0]);

    for (unsigned i = threadIdx.x; i < 2048u; i += blockDim.x) {
        unsigned c = s_whist[i];
        if (c) atomicAdd(&g_whist[i], c);
    }
}

// ---------------------------------------------------------------------------
// Persistent tail: one region stream + one grid barrier.
__global__ void __launch_bounds__(NTHREADS, 8)
resolve_kernel(const float* __restrict__ xs,
               const float* __restrict__ ms,
               const int* __restrict__ t_ptr,
               const float* __restrict__ sparsity,
               float* __restrict__ out,
               unsigned n) {
    __shared__ unsigned ss[NTHREADS];
    __shared__ unsigned sh[4096];
    __shared__ uint2    stash[STASH_MAX];
    __shared__ unsigned sb1, sr1, s_stash;
    __shared__ unsigned sv[4];
    int t = threadIdx.x;

    // ---- select fine bin b1 + r1 from g_whist + g_below ----
    if (t == 0) { sb1 = 0xFFFFFFFFu; sr1 = 1u; s_stash = 0u; }
    unsigned c[8];
    unsigned local = 0u;
    #pragma unroll
    for (int j = 0; j < 8; j++) { c[j] = g_whist[t * 8 + j]; local += c[j]; }
    ss[t] = local;
    __syncthreads();
    for (int off = 1; off < NTHREADS; off <<= 1) {
        unsigned v = (t >= off) ? ss[t - off] : 0u;
        __syncthreads();
        ss[t] += v;
        __syncthreads();
    }
    unsigned incl   = ss[t];
    unsigned total  = ss[NTHREADS - 1];
    unsigned before = incl - local;

    unsigned below = g_below;
    unsigned R = rank_R(sparsity, n);
    bool fb = (below >= R) || ((R - below) > total) || (g_ovf != 0u);
    unsigned Rp = R - below;

    if (!fb && Rp > before && Rp <= incl) {
        unsigned run = before;
        #pragma unroll
        for (int j = 0; j < 8; j++) {
            if (Rp <= run + c[j]) {
                sb1 = (unsigned)(t * 8 + j);
                sr1 = Rp - run;
                break;
            }
            run += c[j];
        }
    }
    __syncthreads();

    // ---- fallback: block 0 exact 3-level radix over full data ----
    if (fb) {
        if (blockIdx.x != 0) return;
        float tf = read_tf(t_ptr);

        for (unsigned i = t; i < 4096u; i += blockDim.x) sh[i] = 0u;
        __syncthreads();
        for (unsigned i = t; i < n; i += blockDim.x)
            atomicAdd(&sh[key_of(xs[i], ms[i], tf) >> 20], 1u);
        __syncthreads();
        if (t == 0) {
            unsigned run = 0u;
            for (unsigned b = 0; b < 4096u; b++) {
                if (R <= run + sh[b]) { sv[0] = b; sv[1] = R - run; break; }
                run += sh[b];
            }
        }
        __syncthreads();
        unsigned b1 = sv[0], r1 = sv[1];

        for (unsigned i = t; i < 1024u; i += blockDim.x) sh[i] = 0u;
        __syncthreads();
        for (unsigned i = t; i < n; i += blockDim.x) {
            unsigned k = key_of(xs[i], ms[i], tf);
            if ((k >> 20) == b1) atomicAdd(&sh[(k >> 10) & 1023u], 1u);
        }
        __syncthreads();
        if (t == 0) {
            unsigned run = 0u;
            for (unsigned b = 0; b < 1024u; b++) {
                if (r1 <= run + sh[b]) { sv[2] = b; sv[1] = r1 - run; break; }
                run += sh[b];
            }
        }
        __syncthreads();
        unsigned b2 = sv[2], r2 = sv[1];
        unsigned pre = (b1 << 10) | b2;

        for (unsigned i = t; i < 1024u; i += blockDim.x) sh[i] = 0u;
        __syncthreads();
        for (unsigned i = t; i < n; i += blockDim.x) {
            unsigned k = key_of(xs[i], ms[i], tf);
            if ((k >> 10) == pre) atomicAdd(&sh[k & 1023u], 1u);
        }
        __syncthreads();
        if (t == 0) {
            unsigned run = 0u;
            for (unsigned b = 0; b < 1024u; b++) {
                if (r2 <= run + sh[b]) { sv[3] = (pre << 10) | b; break; }
                run += sh[b];
            }
        }
        __syncthreads();
        unsigned thr = sv[3];
        for (unsigned i = t; i < n; i += blockDim.x) {
            unsigned k = key_of(xs[i], ms[i], tf);
            out[i] = (k >= thr) ? xs[i] : 0.0f;
        }
        return;
    }

    unsigned b1 = sb1;
    unsigned r1 = sr1;
    unsigned k_lo = g_klo;
    unsigned fs   = g_fs;
    unsigned nlow = 1u << fs;                      // <= 4096
    unsigned b1start = k_lo + (b1 << fs);
    unsigned b1end   = b1start + (1u << fs);
    unsigned lowmask = nlow - 1u;
    unsigned cnt    = g_blk_cnt[blockIdx.x];
    unsigned region = blockIdx.x * PER_BLOCK;

    // ---- phase A: single region stream ----
    for (unsigned i = t; i < nlow; i += blockDim.x) sh[i] = 0u;
    __syncthreads();
    for (unsigned j = (unsigned)t; j < cnt; j += blockDim.x) {
        uint2 r = g_cand[region + j];
        if (r.x >= b1end) out[r.y] = xs[r.y];
        else if (r.x >= b1start) {
            agg_shared_add(sh, r.x & lowmask);
            unsigned pos = atomicAdd(&s_stash, 1u);
            if (pos < STASH_MAX) stash[pos] = r;
        }
    }
    __syncthreads();
    for (unsigned i = t; i < nlow; i += blockDim.x) {
        unsigned h = sh[i];
        if (h) atomicAdd(&g_lowh[i], h);
    }
    __threadfence();
    __syncthreads();
    if (t == 0) atomicAdd(&g_d2, 1u);

    // ---- block 0: exact threshold from low hist ----
    if (blockIdx.x == 0) {
        if (t == 0) { while (atomicAdd(&g_d2, 0u) < gridDim.x) {} }
        __syncthreads();
        unsigned q[16];
        unsigned loc = 0u;
        #pragma unroll
        for (int j = 0; j < 16; j++) { q[j] = g_lowh[t * 16 + j]; loc += q[j]; }
        ss[t] = loc;
        __syncthreads();
        for (int off = 1; off < NTHREADS; off <<= 1) {
            unsigned v = (t >= off) ? ss[t - off] : 0u;
            __syncthreads();
            ss[t] += v;
            __syncthreads();
        }
        unsigned inc3 = ss[t];
        unsigned bef3 = inc3 - loc;
        if (r1 > bef3 && r1 <= inc3) {
            unsigned run = bef3;
            #pragma unroll
            for (int j = 0; j < 16; j++) {
                if (r1 <= run + q[j]) {
                    g_thr_key = b1start + (unsigned)(t * 16 + j);
                    break;
                }
                run += q[j];
            }
        }
        __syncthreads();
        if (t == 0) { __threadfence(); atomicExch(&g_rdy2, 1u); }
    }

    // ---- apply thr to stashed b1 cands ----
    if (t == 0) { while (atomicAdd(&g_rdy2, 0u) == 0u) {} }
    __syncthreads();
    unsigned thr = g_thr_key;
    unsigned nst = s_stash;
    if (nst <= STASH_MAX) {
        for (unsigned j = (unsigned)t; j < nst; j += blockDim.x) {
            uint2 r = stash[j];
            if (r.x >= thr) out[r.y] = xs[r.y];
        }
    } else {
        for (unsigned j = (unsigned)t; j < cnt; j += blockDim.x) {
            uint2 r = g_cand[region + j];
            if (r.x >= thr && r.x < b1end) out[r.y] = xs[r.y];
        }
    }
}

// ---------------------------------------------------------------------------
extern "C" void kernel_launch(void* const* d_in, const int* in_sizes, int n_in,
                              void* d_out, int out_size) {
    const float* xs = (const float*)d_in[0];
    const float* ms = (const float*)d_in[1];
    const float* sp = (const float*)d_in[2];
    // d_in[3] = mask (unused by the reference computation)
    const int* t_ptr = (n_in >= 5) ? (const int*)d_in[4] : nullptr;

    unsigned n = (unsigned)in_sizes[0];
    float* out = (float*)d_out;

    zero_kernel<<<4, 1024>>>();
    sample_kernel<<<264, 256>>>(xs, ms, t_ptr, sp, n);
    passA_kernel<<<NBLOCKS, NTHREADS>>>(xs, ms, t_ptr, out, n);
    resolve_kernel<<<NBLOCKS, NTHREADS>>>(xs, ms, t_ptr, sp, out, n);
}

// round 12
// speedup vs baseline: 1.4089x; 1.2328x over previous
#include <cuda_runtime.h>
#include <stdint.h>

// ---------------------------------------------------------------------------
// MagnitudePruning via 2-level-sampled key-window radix select on
// s = t*magnitude + |x|  (monotone surrogate; uniform divide preserves rank).
//
// zero    : clear small histograms/counters
// sample  : persistent 2-phase, chunked coalesced sampling (1M samples):
//           coarse 4096-bin hist -> coarse window -> runtime shift fs ->
//           fine 4096-bin hist (samples L2-hot) -> key window [k_lo,k_hi)
// passA   : ONE full fused pass (R9-proven tiled staging): exact
//           below-count, final out for out-of-window, compact window cands
//           {key,idx,xbits} to per-block regions, 2048-bin fine whist
// resolve : persistent: select fine bin b1+r1; ONE region stream (finalize
//           key>=b1_end via stored xbits -- NO gather), stash+low-hist b1
//           cands; block0 -> exact thr; apply from stash.
//           Exact single-block fallback on any miss/overflow.
// ---------------------------------------------------------------------------

#define NBLOCKS    1184u
#define NTHREADS   256u
#define TILE_F4    512u
#define PER_BLOCK  40960u
#define SBUF_MAX   512u
#define STASH_MAX  512u
#define NCHUNKS    2048u
#define CHUNK_F4   128u

__device__ unsigned g_coarse[4096];
__device__ unsigned g_fine[4096];
__device__ unsigned g_whist[2048];
__device__ unsigned g_lowh[4096];
__device__ unsigned g_below;
__device__ unsigned g_done1, g_done2, g_d2;
__device__ unsigned g_s2r, g_rdy2;
__device__ unsigned g_ovf;
__device__ unsigned g_wbase, g_fs, g_tlo, g_thi;
__device__ unsigned g_klo, g_khi;
__device__ unsigned g_thr_key;
__device__ unsigned g_blk_cnt[NBLOCKS];
__device__ uint4    g_cand[NBLOCKS * PER_BLOCK];   // {key, idx, xbits, 0}

__device__ __forceinline__ unsigned key_of(float x, float m, float tf) {
    float s = __fadd_rn(__fmul_rn(tf, m), fabsf(x));
    return __float_as_uint(s);
}
__device__ __forceinline__ float read_tf(const int* t_ptr) {
    return t_ptr ? (float)(*t_ptr) : 1.0f;
}
__device__ __forceinline__ unsigned rank_R(const float* sp, unsigned n) {
    float fidx = floorf(__fsub_rn(__fmul_rn(sp[0], (float)n), 1.0f));
    long long idx = (long long)fidx;
    if (idx < 0) idx = 0;
    if (idx > (long long)(n - 1)) idx = (long long)(n - 1);
    return (unsigned)idx + 1u;
}
__device__ __forceinline__ void agg_shared_add(unsigned* hist, unsigned bin) {
    unsigned act    = __activemask();
    unsigned peers  = __match_any_sync(act, bin);
    int      leader = __ffs(peers) - 1;
    if ((int)(threadIdx.x & 31) == leader)
        atomicAdd(&hist[bin], (unsigned)__popc(peers));
}

// ---------------------------------------------------------------------------
__global__ void zero_kernel() {
    unsigned tid = blockIdx.x * blockDim.x + threadIdx.x;
    unsigned stride = gridDim.x * blockDim.x;
    for (unsigned i = tid; i < 4096u; i += stride) { g_coarse[i] = 0u; g_fine[i] = 0u; g_lowh[i] = 0u; }
    for (unsigned i = tid; i < 2048u; i += stride) g_whist[i] = 0u;
    if (tid == 0) {
        g_below = 0u; g_done1 = 0u; g_done2 = 0u; g_d2 = 0u;
        g_s2r = 0u; g_rdy2 = 0u; g_ovf = 0u;
    }
}

// ---------------------------------------------------------------------------
// Persistent 2-phase sampling kernel. 264 blocks (all resident).
__global__ void __launch_bounds__(NTHREADS, 2)
sample_kernel(const float* __restrict__ xs,
              const float* __restrict__ ms,
              const int* __restrict__ t_ptr,
              const float* __restrict__ sparsity,
              unsigned n) {
    __shared__ unsigned sh[4096];
    __shared__ unsigned sscan[256];
    __shared__ unsigned svlo, svhi, svS;
    for (unsigned i = threadIdx.x; i < 4096u; i += blockDim.x) sh[i] = 0u;
    __syncthreads();

    float tf = read_tf(t_ptr);
    unsigned n4 = n >> 2;
    unsigned nsamp4 = NCHUNKS * CHUNK_F4;
    bool small = (n4 < nsamp4);
    const float4* x4 = (const float4*)xs;
    const float4* m4 = (const float4*)ms;
    unsigned gstride = gridDim.x * blockDim.x;
    int t = threadIdx.x;
    if (small) nsamp4 = n4;

    // ---- phase 1: coarse hist (top 12 bits) ----
    for (unsigned i = blockIdx.x * blockDim.x + t; i < nsamp4; i += gstride) {
        unsigned idx;
        if (small) idx = i;
        else {
            unsigned chunk = i >> 7;
            unsigned off   = i & (CHUNK_F4 - 1u);
            idx = (unsigned)(((unsigned long long)chunk * n4) / NCHUNKS) + off;
        }
        float4 xv = x4[idx];
        float4 mv = m4[idx];
        agg_shared_add(sh, key_of(xv.x, mv.x, tf) >> 20);
        agg_shared_add(sh, key_of(xv.y, mv.y, tf) >> 20);
        agg_shared_add(sh, key_of(xv.z, mv.z, tf) >> 20);
        agg_shared_add(sh, key_of(xv.w, mv.w, tf) >> 20);
    }
    __syncthreads();
    for (unsigned i = t; i < 4096u; i += blockDim.x) {
        unsigned c = sh[i];
        if (c) atomicAdd(&g_coarse[i], c);
    }
    __threadfence();

    __shared__ unsigned slast;
    if (t == 0)
        slast = (atomicAdd(&g_done1, 1u) == gridDim.x - 1u) ? 1u : 0u;
    __syncthreads();

    unsigned R = rank_R(sparsity, n);

    if (slast) {
        unsigned loc[16];
        unsigned lsum = 0u;
        #pragma unroll
        for (int j = 0; j < 16; j++) { loc[j] = g_coarse[t * 16 + j]; lsum += loc[j]; }
        sscan[t] = lsum;
        __syncthreads();
        for (int off = 1; off < 256; off <<= 1) {
            unsigned v = (t >= off) ? sscan[t - off] : 0u;
            __syncthreads();
            sscan[t] += v;
            __syncthreads();
        }
        unsigned incl  = sscan[t];
        unsigned total = sscan[255];
        unsigned before = incl - lsum;

        float f = (float)R / (float)n;
        float tlo = (f - 0.003f) * (float)total;
        float thi = (f + 0.003f) * (float)total + 1.0f;
        unsigned slo = (tlo < 1.0f) ? 1u : (unsigned)tlo;
        if (slo > total) slo = total;
        unsigned shi = (thi < 1.0f) ? 1u : (unsigned)thi;
        if (shi > total) shi = total;
        if (shi < slo) shi = slo;

        if (slo > before && slo <= incl) {
            unsigned run = before;
            #pragma unroll
            for (int j = 0; j < 16; j++) {
                if (slo <= run + loc[j]) { svlo = (unsigned)(t * 16 + j); svS = run; break; }
                run += loc[j];
            }
        }
        if (shi > before && shi <= incl) {
            unsigned run = before;
            #pragma unroll
            for (int j = 0; j < 16; j++) {
                if (shi <= run + loc[j]) { svhi = (unsigned)(t * 16 + j); break; }
                run += loc[j];
            }
        }
        __syncthreads();
        if (t == 0) {
            unsigned blo = svlo, bhi = svhi;
            if (bhi < blo) bhi = blo;
            if (bhi - blo + 1u > 16u) bhi = blo + 15u;
            unsigned span = bhi - blo + 1u;
            unsigned fs = 8u;
            while ((((unsigned long long)span << 20) >> fs) > 4096ull) fs++;
            g_wbase = blo << 20;
            g_fs = fs;
            g_tlo = slo - svS;
            g_thi = (shi > svS) ? (shi - svS) : 1u;
            __threadfence();
            atomicExch(&g_s2r, 1u);
        }
    }

    // ---- phase 2: fine hist over window (samples L2-hot) ----
    if (t == 0) { while (atomicAdd(&g_s2r, 0u) == 0u) {} }
    __syncthreads();
    unsigned wbase = g_wbase;
    unsigned fs    = g_fs;

    for (unsigned i = t; i < 4096u; i += blockDim.x) sh[i] = 0u;
    __syncthreads();
    for (unsigned i = blockIdx.x * blockDim.x + t; i < nsamp4; i += gstride) {
        unsigned idx;
        if (small) idx = i;
        else {
            unsigned chunk = i >> 7;
            unsigned off   = i & (CHUNK_F4 - 1u);
            idx = (unsigned)(((unsigned long long)chunk * n4) / NCHUNKS) + off;
        }
        float4 xv = x4[idx];
        float4 mv = m4[idx];
        unsigned kk[4];
        kk[0] = key_of(xv.x, mv.x, tf);
        kk[1] = key_of(xv.y, mv.y, tf);
        kk[2] = key_of(xv.z, mv.z, tf);
        kk[3] = key_of(xv.w, mv.w, tf);
        #pragma unroll
        for (int j = 0; j < 4; j++) {
            if (kk[j] >= wbase) {
                unsigned b = (kk[j] - wbase) >> fs;
                if (b < 4096u) agg_shared_add(sh, b);
            }
        }
    }
    __syncthreads();
    for (unsigned i = t; i < 4096u; i += blockDim.x) {
        unsigned c = sh[i];
        if (c) atomicAdd(&g_fine[i], c);
    }
    __threadfence();

    __shared__ unsigned slast2;
    if (t == 0)
        slast2 = (atomicAdd(&g_done2, 1u) == gridDim.x - 1u) ? 1u : 0u;
    __syncthreads();
    if (!slast2) return;

    // ---- last block: fine window -> exact key bounds ----
    {
        unsigned loc[16];
        unsigned lsum = 0u;
        #pragma unroll
        for (int j = 0; j < 16; j++) { loc[j] = g_fine[t * 16 + j]; lsum += loc[j]; }
        sscan[t] = lsum;
        __syncthreads();
        for (int off = 1; off < 256; off <<= 1) {
            unsigned v = (t >= off) ? sscan[t - off] : 0u;
            __syncthreads();
            sscan[t] += v;
            __syncthreads();
        }
        unsigned incl  = sscan[t];
        unsigned total = sscan[255];
        unsigned before = incl - lsum;

        if (t == 0) { svlo = 0u; svhi = 2047u; }
        __syncthreads();

        if (total > 0u) {
            unsigned tl = g_tlo; if (tl < 1u) tl = 1u; if (tl > total) tl = total;
            unsigned th = g_thi; if (th < tl) th = tl; if (th > total) th = total;
            if (tl > before && tl <= incl) {
                unsigned run = before;
                #pragma unroll
                for (int j = 0; j < 16; j++) {
                    if (tl <= run + loc[j]) { svlo = (unsigned)(t * 16 + j); break; }
                    run += loc[j];
                }
            }
            if (th > before && th <= incl) {
                unsigned run = before;
                #pragma unroll
                for (int j = 0; j < 16; j++) {
                    if (th <= run + loc[j]) { svhi = (unsigned)(t * 16 + j); break; }
                    run += loc[j];
                }
            }
        }
        __syncthreads();
        if (t == 0) {
            unsigned flo = svlo, fhi = svhi;
            if (fhi < flo) fhi = flo;
            if (fhi - flo > 2047u) fhi = flo + 2047u;
            g_klo = wbase + (flo << fs);
            g_khi = wbase + ((fhi + 1u) << fs);
        }
    }
}

// ---------------------------------------------------------------------------
// The single fused full pass (R9 structure; candidates carry xbits).
__global__ void __launch_bounds__(NTHREADS, 8)
passA_kernel(const float* __restrict__ xs,
             const float* __restrict__ ms,
             const int* __restrict__ t_ptr,
             float* __restrict__ out,
             unsigned n) {
    __shared__ uint4    s_buf[SBUF_MAX];
    __shared__ unsigned s_whist[2048];
    __shared__ unsigned s_cnt;
    __shared__ unsigned s_red[NTHREADS];

    for (unsigned i = threadIdx.x; i < 2048u; i += blockDim.x) s_whist[i] = 0u;

    float tf = read_tf(t_ptr);
    unsigned k_lo = g_klo, k_hi = g_khi;
    unsigned fs = g_fs;
    unsigned n4 = n >> 2;
    const float4* x4 = (const float4*)xs;
    const float4* m4 = (const float4*)ms;
    float4* o4 = (float4*)out;

    unsigned region = blockIdx.x * PER_BLOCK;
    unsigned nreg = 0u;
    unsigned below = 0u;
    unsigned ntiles = (n4 + TILE_F4 - 1u) / TILE_F4;

    for (unsigned tile = blockIdx.x; tile < ntiles; tile += gridDim.x) {
        if (threadIdx.x == 0) s_cnt = 0u;
        __syncthreads();

        unsigned tbase = tile * TILE_F4;
        #pragma unroll
        for (int k = 0; k < 2; k++) {
            unsigned i = tbase + (unsigned)k * NTHREADS + threadIdx.x;
            if (i < n4) {
                float4 xv = __ldcs(&x4[i]);
                float4 mv = __ldcs(&m4[i]);
                unsigned e = i * 4u;
                unsigned kk[4];
                kk[0] = key_of(xv.x, mv.x, tf);
                kk[1] = key_of(xv.y, mv.y, tf);
                kk[2] = key_of(xv.z, mv.z, tf);
                kk[3] = key_of(xv.w, mv.w, tf);
                float vv[4] = {xv.x, xv.y, xv.z, xv.w};
                float ov[4];
                #pragma unroll
                for (int j = 0; j < 4; j++) {
                    unsigned key = kk[j];
                    below += (key < k_lo) ? 1u : 0u;
                    ov[j] = (key >= k_hi) ? vv[j] : 0.0f;
                    if (key >= k_lo && key < k_hi) {
                        unsigned pos = atomicAdd(&s_cnt, 1u);
                        if (pos < SBUF_MAX)
                            s_buf[pos] = make_uint4(key, e + (unsigned)j,
                                                    __float_as_uint(vv[j]), 0u);
                        agg_shared_add(s_whist, (key - k_lo) >> fs);
                    }
                }
                __stcs(&o4[i], make_float4(ov[0], ov[1], ov[2], ov[3]));
            }
        }
        __syncthreads();

        unsigned cnt = s_cnt;
        if (cnt > SBUF_MAX) {
            if (threadIdx.x == 0) atomicExch(&g_ovf, 1u);
            cnt = SBUF_MAX;
        }
        if (cnt) {
            if (nreg + cnt <= PER_BLOCK) {
                for (unsigned j = threadIdx.x; j < cnt; j += blockDim.x)
                    g_cand[region + nreg + j] = s_buf[j];
                nreg += cnt;
            } else {
                if (threadIdx.x == 0) atomicExch(&g_ovf, 1u);
            }
        }
        __syncthreads();
    }

    // scalar tail (n % 4)
    if (blockIdx.x == 0 && threadIdx.x == 0) {
        for (unsigned i = n4 << 2; i < n; i++) {
            float xv = xs[i];
            unsigned key = key_of(xv, ms[i], tf);
            below += (key < k_lo) ? 1u : 0u;
            out[i] = (key >= k_hi) ? xv : 0.0f;
            if (key >= k_lo && key < k_hi) {
                if (nreg < PER_BLOCK) {
                    g_cand[region + nreg] = make_uint4(key, i, __float_as_uint(xv), 0u);
                    nreg++;
                    atomicAdd(&s_whist[(key - k_lo) >> fs], 1u);
                } else {
                    atomicExch(&g_ovf, 1u);
                }
            }
        }
    }
    __syncthreads();

    if (threadIdx.x == 0) g_blk_cnt[blockIdx.x] = nreg;

    s_red[threadIdx.x] = below;
    __syncthreads();
    for (int off = NTHREADS / 2; off > 0; off >>= 1) {
        if ((int)threadIdx.x < off) s_red[threadIdx.x] += s_red[threadIdx.x + off];
        __syncthreads();
    }
    if (threadIdx.x == 0 && s_red[0]) atomicAdd(&g_below, s_red[0]);

    for (unsigned i = threadIdx.x; i < 2048u; i += blockDim.x) {
        unsigned c = s_whist[i];
        if (c) atomicAdd(&g_whist[i], c);
    }
}

// ---------------------------------------------------------------------------
// Persistent tail: one region stream (store-only finalize) + one grid barrier.
__global__ void __launch_bounds__(NTHREADS, 8)
resolve_kernel(const float* __restrict__ xs,
               const float* __restrict__ ms,
               const int* __restrict__ t_ptr,
               const float* __restrict__ sparsity,
               float* __restrict__ out,
               unsigned n) {
    __shared__ unsigned ss[NTHREADS];
    __shared__ unsigned sh[4096];
    __shared__ uint4    stash[STASH_MAX];
    __shared__ unsigned sb1, sr1, s_stash;
    __shared__ unsigned sv[4];
    int t = threadIdx.x;

    // ---- select fine bin b1 + r1 from g_whist + g_below ----
    if (t == 0) { sb1 = 0xFFFFFFFFu; sr1 = 1u; s_stash = 0u; }
    unsigned c[8];
    unsigned local = 0u;
    #pragma unroll
    for (int j = 0; j < 8; j++) { c[j] = g_whist[t * 8 + j]; local += c[j]; }
    ss[t] = local;
    __syncthreads();
    for (int off = 1; off < NTHREADS; off <<= 1) {
        unsigned v = (t >= off) ? ss[t - off] : 0u;
        __syncthreads();
        ss[t] += v;
        __syncthreads();
    }
    unsigned incl   = ss[t];
    unsigned total  = ss[NTHREADS - 1];
    unsigned before = incl - local;

    unsigned below = g_below;
    unsigned R = rank_R(sparsity, n);
    bool fb = (below >= R) || ((R - below) > total) || (g_ovf != 0u);
    unsigned Rp = R - below;

    if (!fb && Rp > before && Rp <= incl) {
        unsigned run = before;
        #pragma unroll
        for (int j = 0; j < 8; j++) {
            if (Rp <= run + c[j]) {
                sb1 = (unsigned)(t * 8 + j);
                sr1 = Rp - run;
                break;
            }
            run += c[j];
        }
    }
    __syncthreads();

    // ---- fallback: block 0 exact 3-level radix over full data ----
    if (fb) {
        if (blockIdx.x != 0) return;
        float tf = read_tf(t_ptr);

        for (unsigned i = t; i < 4096u; i += blockDim.x) sh[i] = 0u;
        __syncthreads();
        for (unsigned i = t; i < n; i += blockDim.x)
            atomicAdd(&sh[key_of(xs[i], ms[i], tf) >> 20], 1u);
        __syncthreads();
        if (t == 0) {
            unsigned run = 0u;
            for (unsigned b = 0; b < 4096u; b++) {
                if (R <= run + sh[b]) { sv[0] = b; sv[1] = R - run; break; }
                run += sh[b];
            }
        }
        __syncthreads();
        unsigned b1 = sv[0], r1 = sv[1];

        for (unsigned i = t; i < 1024u; i += blockDim.x) sh[i] = 0u;
        __syncthreads();
        for (unsigned i = t; i < n; i += blockDim.x) {
            unsigned k = key_of(xs[i], ms[i], tf);
            if ((k >> 20) == b1) atomicAdd(&sh[(k >> 10) & 1023u], 1u);
        }
        __syncthreads();
        if (t == 0) {
            unsigned run = 0u;
            for (unsigned b = 0; b < 1024u; b++) {
                if (r1 <= run + sh[b]) { sv[2] = b; sv[1] = r1 - run; break; }
                run += sh[b];
            }
        }
        __syncthreads();
        unsigned b2 = sv[2], r2 = sv[1];
        unsigned pre = (b1 << 10) | b2;

        for (unsigned i = t; i < 1024u; i += blockDim.x) sh[i] = 0u;
        __syncthreads();
        for (unsigned i = t; i < n; i += blockDim.x) {
            unsigned k = key_of(xs[i], ms[i], tf);
            if ((k >> 10) == pre) atomicAdd(&sh[k & 1023u], 1u);
        }
        __syncthreads();
        if (t == 0) {
            unsigned run = 0u;
            for (unsigned b = 0; b < 1024u; b++) {
                if (r2 <= run + sh[b]) { sv[3] = (pre << 10) | b; break; }
                run += sh[b];
            }
        }
        __syncthreads();
        unsigned thr = sv[3];
        for (unsigned i = t; i < n; i += blockDim.x) {
            unsigned k = key_of(xs[i], ms[i], tf);
            out[i] = (k >= thr) ? xs[i] : 0.0f;
        }
        return;
    }

    unsigned b1 = sb1;
    unsigned r1 = sr1;
    unsigned k_lo = g_klo;
    unsigned fs   = g_fs;
    unsigned nlow = 1u << fs;                      // <= 4096
    unsigned b1start = k_lo + (b1 << fs);
    unsigned b1end   = b1start + (1u << fs);
    unsigned lowmask = nlow - 1u;
    unsigned cnt    = g_blk_cnt[blockIdx.x];
    unsigned region = blockIdx.x * PER_BLOCK;

    // ---- phase A: single region stream; finalize via stored xbits ----
    for (unsigned i = t; i < nlow; i += blockDim.x) sh[i] = 0u;
    __syncthreads();
    for (unsigned j = (unsigned)t; j < cnt; j += blockDim.x) {
        uint4 r = g_cand[region + j];
        if (r.x >= b1end) out[r.y] = __uint_as_float(r.z);
        else if (r.x >= b1start) {
            agg_shared_add(sh, r.x & lowmask);
            unsigned pos = atomicAdd(&s_stash, 1u);
            if (pos < STASH_MAX) stash[pos] = r;
        }
    }
    __syncthreads();
    for (unsigned i = t; i < nlow; i += blockDim.x) {
        unsigned h = sh[i];
        if (h) atomicAdd(&g_lowh[i], h);
    }
    __threadfence();
    __syncthreads();
    if (t == 0) atomicAdd(&g_d2, 1u);

    // ---- block 0: exact threshold from low hist ----
    if (blockIdx.x == 0) {
        if (t == 0) { while (atomicAdd(&g_d2, 0u) < gridDim.x) {} }
        __syncthreads();
        unsigned q[16];
        unsigned loc = 0u;
        #pragma unroll
        for (int j = 0; j < 16; j++) { q[j] = g_lowh[t * 16 + j]; loc += q[j]; }
        ss[t] = loc;
        __syncthreads();
        for (int off = 1; off < NTHREADS; off <<= 1) {
            unsigned v = (t >= off) ? ss[t - off] : 0u;
            __syncthreads();
            ss[t] += v;
            __syncthreads();
        }
        unsigned inc3 = ss[t];
        unsigned bef3 = inc3 - loc;
        if (r1 > bef3 && r1 <= inc3) {
            unsigned run = bef3;
            #pragma unroll
            for (int j = 0; j < 16; j++) {
                if (r1 <= run + q[j]) {
                    g_thr_key = b1start + (unsigned)(t * 16 + j);
                    break;
                }
                run += q[j];
            }
        }
        __syncthreads();
        if (t == 0) { __threadfence(); atomicExch(&g_rdy2, 1u); }
    }

    // ---- apply thr to stashed b1 cands (store-only) ----
    if (t == 0) { while (atomicAdd(&g_rdy2, 0u) == 0u) {} }
    __syncthreads();
    unsigned thr = g_thr_key;
    unsigned nst = s_stash;
    if (nst <= STASH_MAX) {
        for (unsigned j = (unsigned)t; j < nst; j += blockDim.x) {
            uint4 r = stash[j];
            if (r.x >= thr) out[r.y] = __uint_as_float(r.z);
        }
    } else {
        for (unsigned j = (unsigned)t; j < cnt; j += blockDim.x) {
            uint4 r = g_cand[region + j];
            if (r.x >= thr && r.x < b1end) out[r.y] = __uint_as_float(r.z);
        }
    }
}

// ---------------------------------------------------------------------------
extern "C" void kernel_launch(void* const* d_in, const int* in_sizes, int n_in,
                              void* d_out, int out_size) {
    const float* xs = (const float*)d_in[0];
    const float* ms = (const float*)d_in[1];
    const float* sp = (const float*)d_in[2];
    // d_in[3] = mask (unused by the reference computation)
    const int* t_ptr = (n_in >= 5) ? (const int*)d_in[4] : nullptr;

    unsigned n = (unsigned)in_sizes[0];
    float* out = (float*)d_out;

    zero_kernel<<<4, 1024>>>();
    sample_kernel<<<264, 256>>>(xs, ms, t_ptr, sp, n);
    passA_kernel<<<NBLOCKS, NTHREADS>>>(xs, ms, t_ptr, out, n);
    resolve_kernel<<<NBLOCKS, NTHREADS>>>(xs, ms, t_ptr, sp, out, n);
}